// round 3
// baseline (speedup 1.0000x reference)
#include <cuda_runtime.h>
#include <math.h>

// ---------------- problem constants ----------------
#define NB   16          // batch
#define LSEQ 256         // sequence length (TY+1)
#define ENC  512
#define EMB  256
#define DEC  512
#define NV   32000
#define G4   2048        // 4*DEC
#define MROWS 4096       // NB*LSEQ

// ---------------- scratch (__device__ globals; no allocs) ----------------
__device__ float g_seq [NB*LSEQ*EMB];        //  4 MB  [b][t][EMB]
__device__ float g_xw  [LSEQ*G4*NB];         // 32 MB  [t][j][b]
__device__ float g_cat [NB*LSEQ*2*DEC];      // 16 MB  [b][t][ mix(512) | h1(512) ]
__device__ float g_attn[MROWS*DEC];          //  8 MB  [m][512]
__device__ float g_h2  [MROWS*DEC];          //  8 MB  [m][512]
__device__ float g_hbuf[2*NB*DEC];           // h double buffer
__device__ unsigned          g_bar_cnt;
__device__ volatile unsigned g_bar_gen;

__device__ __forceinline__ float sigf(float x){ return 1.0f/(1.0f+__expf(-x)); }

// ---------------- grid barrier (self-resetting, capture-safe) ----------------
__device__ __forceinline__ void grid_barrier()
{
    __syncthreads();
    if (threadIdx.x == 0) {
        __threadfence();
        unsigned gen = g_bar_gen;
        if (atomicAdd(&g_bar_cnt, 1u) == gridDim.x - 1u) {
            atomicExch(&g_bar_cnt, 0u);
            __threadfence();
            g_bar_gen = gen + 1u;
        } else {
            while (g_bar_gen == gen) { }
        }
    }
    __syncthreads();
}

// ---------------- kernel 1: fc1 + BatchNorm (batch stats) -> seq[:,0,:] ----------------
__global__ void __launch_bounds__(256) fc1_bn_kernel(
    const float* __restrict__ x,     // [16,512]
    const float* __restrict__ w,     // [256,512]
    const float* __restrict__ bias,  // [256]
    const float* __restrict__ gam,   // [256]
    const float* __restrict__ bet)   // [256]
{
    __shared__ float xs[NB*ENC];     // 32 KB
    int tid = threadIdx.x;
    for (int i = tid; i < NB*ENC/4; i += 256)
        ((float4*)xs)[i] = ((const float4*)x)[i];
    __syncthreads();

    int j = tid;                     // one feature per thread (EMB == 256)
    float f[NB];
    #pragma unroll
    for (int b = 0; b < NB; b++) f[b] = bias[j];

    const float4* w4 = (const float4*)(w + j*ENC);
    for (int k4 = 0; k4 < ENC/4; k4++) {
        float4 ww = w4[k4];
        #pragma unroll
        for (int b = 0; b < NB; b++) {
            float4 xx = ((float4*)xs)[b*(ENC/4) + k4];
            f[b] += ww.x*xx.x + ww.y*xx.y + ww.z*xx.z + ww.w*xx.w;
        }
    }
    float mu = 0.f;
    #pragma unroll
    for (int b = 0; b < NB; b++) mu += f[b];
    mu *= (1.0f/NB);
    float var = 0.f;
    #pragma unroll
    for (int b = 0; b < NB; b++) { float d = f[b]-mu; var += d*d; }
    var *= (1.0f/NB);
    float s = rsqrtf(var + 1e-5f) * gam[j];
    float bb = bet[j];
    #pragma unroll
    for (int b = 0; b < NB; b++)
        g_seq[b*(LSEQ*EMB) + j] = (f[b]-mu)*s + bb;   // t = 0
}

// ---------------- kernel 2: embedding gather -> seq[:,1:,:] ----------------
__global__ void embed_kernel(const int* __restrict__ y,      // [16,255]
                             const float* __restrict__ emb)  // [32000,256]
{
    int blk = blockIdx.x;            // 16*255 blocks
    int b = blk / (LSEQ-1), t = blk % (LSEQ-1);
    int row = y[b*(LSEQ-1) + t];
    const float4* src = (const float4*)(emb + (long)row*EMB);
    float4* dst = (float4*)(g_seq + b*(LSEQ*EMB) + (t+1)*EMB);
    dst[threadIdx.x] = src[threadIdx.x];   // 64 threads * float4 = 256 floats
}

// ---------------- kernel 3: SGEMM  C = A[M,K] * B[N,K]^T (+bias) ----------------
// MODE 0: C[m*N+n]   (row-major), optional tanh
// MODE 1: C[t*(N*16) + n*16 + b] with m = b*LSEQ + t   (LSTM xw layout)
template<int MODE, bool DOTANH>
__global__ void __launch_bounds__(256) sgemm_tn(
    const float* __restrict__ A, const float* __restrict__ B,
    const float* __restrict__ bias0, const float* __restrict__ bias1,
    float* __restrict__ C, int M, int N, int K)
{
    __shared__ float As[8][132];
    __shared__ float Bs[8][132];
    int tid = threadIdx.x;
    int bn = blockIdx.x, bm = blockIdx.y;

    int lrow = tid >> 1;
    int colq = (tid & 1) * 4;
    const float* Ag = A + (long)(bm*128 + lrow)*K + colq;
    const float* Bg = B + (long)(bn*128 + lrow)*K + colq;

    int tx = tid & 15, ty = tid >> 4;
    float acc[8][8];
    #pragma unroll
    for (int i = 0; i < 8; i++)
        #pragma unroll
        for (int j = 0; j < 8; j++) acc[i][j] = 0.f;

    for (int k0 = 0; k0 < K; k0 += 8) {
        float4 av = *(const float4*)(Ag + k0);
        float4 bv = *(const float4*)(Bg + k0);
        __syncthreads();
        As[colq+0][lrow] = av.x; As[colq+1][lrow] = av.y;
        As[colq+2][lrow] = av.z; As[colq+3][lrow] = av.w;
        Bs[colq+0][lrow] = bv.x; Bs[colq+1][lrow] = bv.y;
        Bs[colq+2][lrow] = bv.z; Bs[colq+3][lrow] = bv.w;
        __syncthreads();
        #pragma unroll
        for (int k = 0; k < 8; k++) {
            float a[8], br[8];
            *(float4*)&a[0]  = *(float4*)&As[k][ty*8];
            *(float4*)&a[4]  = *(float4*)&As[k][ty*8+4];
            *(float4*)&br[0] = *(float4*)&Bs[k][tx*8];
            *(float4*)&br[4] = *(float4*)&Bs[k][tx*8+4];
            #pragma unroll
            for (int i = 0; i < 8; i++)
                #pragma unroll
                for (int j = 0; j < 8; j++)
                    acc[i][j] += a[i]*br[j];
        }
    }

    int m0 = bm*128 + ty*8;
    int n0 = bn*128 + tx*8;
    float bs[8];
    #pragma unroll
    for (int j = 0; j < 8; j++) {
        float v = 0.f;
        if (bias0) v += bias0[n0+j];
        if (bias1) v += bias1[n0+j];
        bs[j] = v;
    }
    #pragma unroll
    for (int i = 0; i < 8; i++) {
        int m = m0 + i;
        #pragma unroll
        for (int j = 0; j < 8; j++) {
            float v = acc[i][j] + bs[j];
            if (DOTANH) v = tanhf(v);
            int n = n0 + j;
            if (MODE == 0) {
                C[(long)m*N + n] = v;
            } else {
                int b = m >> 8, t = m & 255;
                C[(long)t*(N*NB) + n*NB + b] = v;
            }
        }
    }
}

// ---------------- kernel 4: persistent LSTM (128 CTAs) ----------------
// xw: [t][j][b] (j = gate*512 + d).  CTA c owns d in [4c, 4c+4), all 4 gates, 16 b.
// thread tid = gate*64 + dl*16 + b
#define LSTM_CTAS 128
#define WP 130   // smem row stride in float4
#define HP 130

__global__ void __launch_bounds__(256, 1) lstm_kernel(
    const float* __restrict__ xw,
    const float* __restrict__ Whh,   // [2048,512]
    float* __restrict__ out, long bstr, long tstr)
{
    extern __shared__ float4 smem[];
    float4* ws = smem;               // 16*WP
    float4* hs = smem + 16*WP;       // 16*HP
    float*  gx = (float*)(smem + 16*WP + 16*HP);   // 256 floats

    int tid = threadIdx.x, cta = blockIdx.x;
    int gate = tid >> 6, dl = (tid >> 4) & 3, b = tid & 15;
    int jl = gate*4 + dl;
    int j  = gate*512 + cta*4 + dl;

    // stage this CTA's 16 Whh rows into smem (once)
    for (int i = tid; i < 16*128; i += 256) {
        int r = i >> 7, c = i & 127;
        int jj = (r >> 2)*512 + cta*4 + (r & 3);
        ws[r*WP + c] = ((const float4*)Whh)[jj*128 + c];
    }
    // zero h double-buffer slot 0
    for (int i = cta*256 + tid; i < NB*DEC; i += LSTM_CTAS*256)
        g_hbuf[i] = 0.f;

    float c_reg = 0.f;
    grid_barrier();

    for (int t = 0; t < LSEQ; t++) {
        // stage h(t) from global (L2) into smem
        const float* hsrc = g_hbuf + (t & 1)*(NB*DEC);
        for (int i = tid; i < NB*128; i += 256) {
            int bb = i >> 7, c = i & 127;
            hs[bb*HP + c] = __ldcg(((const float4*)hsrc) + bb*128 + c);
        }
        __syncthreads();

        float acc = xw[(long)t*(G4*NB) + j*NB + b];
        const float4* wr = ws + jl*WP;
        const float4* hr = hs + b*HP;
        #pragma unroll 4
        for (int k4 = 0; k4 < 128; k4++) {
            float4 w4 = wr[k4];
            float4 h4 = hr[k4];
            acc += w4.x*h4.x + w4.y*h4.y + w4.z*h4.z + w4.w*h4.w;
        }
        gx[tid] = acc;
        __syncthreads();

        if (tid < 64) {
            float ig = sigf(gx[tid]);
            float fg = sigf(gx[64 + tid]);
            float gg = tanhf(gx[128 + tid]);
            float og = sigf(gx[192 + tid]);
            c_reg = fg*c_reg + ig*gg;
            float h = og * tanhf(c_reg);
            int ddl = tid >> 4, bb = tid & 15;
            int d = cta*4 + ddl;
            __stcg(&g_hbuf[((t+1) & 1)*(NB*DEC) + bb*DEC + d], h);
            out[bb*bstr + (long)t*tstr + d] = h;
        }
        grid_barrier();
    }
}

// ---------------- kernel 5: causal self-attention (CTA per (q,b)) ----------------
__global__ void __launch_bounds__(256) attn_kernel()
{
    __shared__ float hqs[512];
    __shared__ float sc[256];
    __shared__ float red[256];
    int q = blockIdx.x, b = blockIdx.y;
    int tid = threadIdx.x;
    int nk = q + 1;
    float* catb = g_cat + (long)b*(LSEQ*2*DEC);

    if (tid < 128)
        ((float4*)hqs)[tid] = ((const float4*)(catb + q*1024 + 512))[tid];
    __syncthreads();

    // scores
    int w = tid >> 5, lane = tid & 31;
    for (int k = w; k < nk; k += 8) {
        const float4* hk = (const float4*)(catb + k*1024 + 512);
        float s = 0.f;
        #pragma unroll
        for (int i = 0; i < 4; i++) {
            float4 a = ((float4*)hqs)[lane + 32*i];
            float4 c = hk[lane + 32*i];
            s += a.x*c.x + a.y*c.y + a.z*c.z + a.w*c.w;
        }
        #pragma unroll
        for (int off = 16; off; off >>= 1) s += __shfl_xor_sync(0xffffffffu, s, off);
        if (lane == 0) sc[k] = s;
    }
    __syncthreads();

    // softmax over sc[0..nk)
    float v = (tid < nk) ? sc[tid] : -INFINITY;
    red[tid] = v; __syncthreads();
    #pragma unroll
    for (int s = 128; s; s >>= 1) {
        if (tid < s) red[tid] = fmaxf(red[tid], red[tid+s]);
        __syncthreads();
    }
    float mx = red[0]; __syncthreads();
    float e = (tid < nk) ? __expf(v - mx) : 0.f;
    red[tid] = e; __syncthreads();
    #pragma unroll
    for (int s = 128; s; s >>= 1) {
        if (tid < s) red[tid] += red[tid+s];
        __syncthreads();
    }
    float inv = 1.f / red[0];
    __syncthreads();
    if (tid < nk) sc[tid] = e * inv;
    __syncthreads();

    // mix = sum_k w[k] * h1[b][k][:]
    float a0 = 0.f, a1 = 0.f;
    for (int k = 0; k < nk; k++) {
        float wk = sc[k];
        const float* hk = catb + k*1024 + 512;
        a0 += wk * hk[tid];
        a1 += wk * hk[tid + 256];
    }
    catb[q*1024 + tid]       = a0;
    catb[q*1024 + tid + 256] = a1;
}

// ---------------- launch ----------------
extern "C" void kernel_launch(void* const* d_in, const int* in_sizes, int n_in,
                              void* d_out, int out_size)
{
    const float* x       = (const float*)d_in[0];
    const int*   y       = (const int*)  d_in[1];
    const float* fc1_w   = (const float*)d_in[2];
    const float* fc1_b   = (const float*)d_in[3];
    const float* bn_g    = (const float*)d_in[4];
    const float* bn_b    = (const float*)d_in[5];
    const float* emb     = (const float*)d_in[6];
    const float* l1_Wih  = (const float*)d_in[7];
    const float* l1_Whh  = (const float*)d_in[8];
    const float* l1_bih  = (const float*)d_in[9];
    const float* l1_bhh  = (const float*)d_in[10];
    const float* attn_W  = (const float*)d_in[11];
    const float* dc_Wih  = (const float*)d_in[12];
    const float* dc_Whh  = (const float*)d_in[13];
    const float* dc_bih  = (const float*)d_in[14];
    const float* dc_bhh  = (const float*)d_in[15];
    const float* fc2_w   = (const float*)d_in[16];
    const float* fc2_b   = (const float*)d_in[17];
    float* out = (float*)d_out;

    float *p_seq, *p_xw, *p_cat, *p_attn, *p_h2;
    cudaGetSymbolAddress((void**)&p_seq,  g_seq);
    cudaGetSymbolAddress((void**)&p_xw,   g_xw);
    cudaGetSymbolAddress((void**)&p_cat,  g_cat);
    cudaGetSymbolAddress((void**)&p_attn, g_attn);
    cudaGetSymbolAddress((void**)&p_h2,   g_h2);

    int lstm_smem = (16*WP + 16*HP)*16 + 256*4;
    cudaFuncSetAttribute(lstm_kernel, cudaFuncAttributeMaxDynamicSharedMemorySize, lstm_smem);

    // 1. fc1 + BN
    fc1_bn_kernel<<<1, 256>>>(x, fc1_w, fc1_b, bn_g, bn_b);
    // 2. embedding
    embed_kernel<<<NB*(LSEQ-1), 64>>>(y, emb);
    // 3. xw1 = seq @ l1_Wih^T + biases   (LSTM layout)
    sgemm_tn<1,false><<<dim3(G4/128, MROWS/128), 256>>>(
        p_seq, l1_Wih, l1_bih, l1_bhh, p_xw, MROWS, G4, EMB);
    // 4. LSTM 1  ->  g_cat[b][t][512:1024]
    lstm_kernel<<<LSTM_CTAS, 256, lstm_smem>>>(
        p_xw, l1_Whh, p_cat + 512, (long)LSEQ*2*DEC, (long)2*DEC);
    // 5. attention -> g_cat[b][t][0:512]
    attn_kernel<<<dim3(LSEQ, NB), 256>>>();
    // 6. attn = tanh(cat @ attn_W^T)
    sgemm_tn<0,true><<<dim3(DEC/128, MROWS/128), 256>>>(
        p_cat, attn_W, nullptr, nullptr, p_attn, MROWS, DEC, 2*DEC);
    // 7. xw2 = attn @ dc_Wih^T + biases  (LSTM layout)
    sgemm_tn<1,false><<<dim3(G4/128, MROWS/128), 256>>>(
        p_attn, dc_Wih, dc_bih, dc_bhh, p_xw, MROWS, G4, DEC);
    // 8. LSTM 2 -> g_h2[m][d]
    lstm_kernel<<<LSTM_CTAS, 256, lstm_smem>>>(
        p_xw, dc_Whh, p_h2, (long)LSEQ*DEC, (long)DEC);
    // 9. fc2 -> d_out
    sgemm_tn<0,false><<<dim3(NV/128, MROWS/128), 256>>>(
        p_h2, fc2_w, fc2_b, nullptr, out, MROWS, NV, DEC);
}

// round 5
// speedup vs baseline: 1.3415x; 1.3415x over previous
#include <cuda_runtime.h>
#include <cuda_bf16.h>
#include <math.h>

// ---------------- problem constants ----------------
#define NB   16          // batch
#define LSEQ 256         // sequence length (TY+1)
#define ENC  512
#define EMB  256
#define DEC  512
#define NV   32000
#define G4   2048        // 4*DEC
#define MROWS 4096       // NB*LSEQ

// ---------------- scratch (__device__ globals; no allocs) ----------------
__device__ float g_seq [NB*LSEQ*EMB];        //  4 MB  [b][t][EMB]
__device__ float g_xw  [LSEQ*G4*NB];         // 32 MB  [t][j][b]
__device__ float g_cat [NB*LSEQ*2*DEC];      // 16 MB  [b][t][ mix(512) | h1(512) ]
__device__ float g_attn[MROWS*DEC];          //  8 MB  [m][512]
__device__ float g_h2  [MROWS*DEC];          //  8 MB  [m][512]
__device__ float g_hbuf[2*NB*DEC];           // h double buffer
__device__ unsigned          g_bar_cnt;
__device__ volatile unsigned g_bar_gen;

// bf16 hi/lo split operands for fc2 tensor-core GEMM
__device__ __nv_bfloat16 g_Ah[MROWS*DEC];    //  4 MB
__device__ __nv_bfloat16 g_Al[MROWS*DEC];    //  4 MB
__device__ __nv_bfloat16 g_Bh[NV*DEC];       // 32 MB
__device__ __nv_bfloat16 g_Bl[NV*DEC];       // 32 MB

__device__ __forceinline__ float sigf(float x){ return 1.0f/(1.0f+__expf(-x)); }

// ---------------- grid barrier (self-resetting, capture-safe) ----------------
__device__ __forceinline__ void grid_barrier()
{
    __syncthreads();
    if (threadIdx.x == 0) {
        __threadfence();
        unsigned gen = g_bar_gen;
        if (atomicAdd(&g_bar_cnt, 1u) == gridDim.x - 1u) {
            atomicExch(&g_bar_cnt, 0u);
            __threadfence();
            g_bar_gen = gen + 1u;
        } else {
            while (g_bar_gen == gen) { }
        }
    }
    __syncthreads();
}

// ---------------- kernel 1: fc1 + BatchNorm (batch stats) -> seq[:,0,:] ----------------
__global__ void __launch_bounds__(256) fc1_bn_kernel(
    const float* __restrict__ x,     // [16,512]
    const float* __restrict__ w,     // [256,512]
    const float* __restrict__ bias,  // [256]
    const float* __restrict__ gam,   // [256]
    const float* __restrict__ bet)   // [256]
{
    __shared__ float xs[NB*ENC];     // 32 KB
    int tid = threadIdx.x;
    for (int i = tid; i < NB*ENC/4; i += 256)
        ((float4*)xs)[i] = ((const float4*)x)[i];
    __syncthreads();

    int j = tid;                     // one feature per thread (EMB == 256)
    float f[NB];
    #pragma unroll
    for (int b = 0; b < NB; b++) f[b] = bias[j];

    const float4* w4 = (const float4*)(w + j*ENC);
    for (int k4 = 0; k4 < ENC/4; k4++) {
        float4 ww = w4[k4];
        #pragma unroll
        for (int b = 0; b < NB; b++) {
            float4 xx = ((float4*)xs)[b*(ENC/4) + k4];
            f[b] += ww.x*xx.x + ww.y*xx.y + ww.z*xx.z + ww.w*xx.w;
        }
    }
    float mu = 0.f;
    #pragma unroll
    for (int b = 0; b < NB; b++) mu += f[b];
    mu *= (1.0f/NB);
    float var = 0.f;
    #pragma unroll
    for (int b = 0; b < NB; b++) { float d = f[b]-mu; var += d*d; }
    var *= (1.0f/NB);
    float s = rsqrtf(var + 1e-5f) * gam[j];
    float bb = bet[j];
    #pragma unroll
    for (int b = 0; b < NB; b++)
        g_seq[b*(LSEQ*EMB) + j] = (f[b]-mu)*s + bb;   // t = 0
}

// ---------------- kernel 2: embedding gather -> seq[:,1:,:] ----------------
__global__ void embed_kernel(const int* __restrict__ y,      // [16,255]
                             const float* __restrict__ emb)  // [32000,256]
{
    int blk = blockIdx.x;            // 16*255 blocks
    int b = blk / (LSEQ-1), t = blk % (LSEQ-1);
    int row = y[b*(LSEQ-1) + t];
    const float4* src = (const float4*)(emb + (long)row*EMB);
    float4* dst = (float4*)(g_seq + b*(LSEQ*EMB) + (t+1)*EMB);
    dst[threadIdx.x] = src[threadIdx.x];   // 64 threads * float4 = 256 floats
}

// ---------------- kernel 3: SGEMM  C = A[M,K] * B[N,K]^T (+bias) ----------------
// MODE 0: C[m*N+n]   (row-major), optional tanh
// MODE 1: C[t*(N*16) + n*16 + b] with m = b*LSEQ + t   (LSTM xw layout)
template<int MODE, bool DOTANH>
__global__ void __launch_bounds__(256) sgemm_tn(
    const float* __restrict__ A, const float* __restrict__ B,
    const float* __restrict__ bias0, const float* __restrict__ bias1,
    float* __restrict__ C, int M, int N, int K)
{
    __shared__ float As[8][132];
    __shared__ float Bs[8][132];
    int tid = threadIdx.x;
    int bn = blockIdx.x, bm = blockIdx.y;

    int lrow = tid >> 1;
    int colq = (tid & 1) * 4;
    const float* Ag = A + (long)(bm*128 + lrow)*K + colq;
    const float* Bg = B + (long)(bn*128 + lrow)*K + colq;

    int tx = tid & 15, ty = tid >> 4;
    float acc[8][8];
    #pragma unroll
    for (int i = 0; i < 8; i++)
        #pragma unroll
        for (int j = 0; j < 8; j++) acc[i][j] = 0.f;

    for (int k0 = 0; k0 < K; k0 += 8) {
        float4 av = *(const float4*)(Ag + k0);
        float4 bv = *(const float4*)(Bg + k0);
        __syncthreads();
        As[colq+0][lrow] = av.x; As[colq+1][lrow] = av.y;
        As[colq+2][lrow] = av.z; As[colq+3][lrow] = av.w;
        Bs[colq+0][lrow] = bv.x; Bs[colq+1][lrow] = bv.y;
        Bs[colq+2][lrow] = bv.z; Bs[colq+3][lrow] = bv.w;
        __syncthreads();
        #pragma unroll
        for (int k = 0; k < 8; k++) {
            float a[8], br[8];
            *(float4*)&a[0]  = *(float4*)&As[k][ty*8];
            *(float4*)&a[4]  = *(float4*)&As[k][ty*8+4];
            *(float4*)&br[0] = *(float4*)&Bs[k][tx*8];
            *(float4*)&br[4] = *(float4*)&Bs[k][tx*8+4];
            #pragma unroll
            for (int i = 0; i < 8; i++)
                #pragma unroll
                for (int j = 0; j < 8; j++)
                    acc[i][j] += a[i]*br[j];
        }
    }

    int m0 = bm*128 + ty*8;
    int n0 = bn*128 + tx*8;
    float bs[8];
    #pragma unroll
    for (int j = 0; j < 8; j++) {
        float v = 0.f;
        if (bias0) v += bias0[n0+j];
        if (bias1) v += bias1[n0+j];
        bs[j] = v;
    }
    #pragma unroll
    for (int i = 0; i < 8; i++) {
        int m = m0 + i;
        #pragma unroll
        for (int j = 0; j < 8; j++) {
            float v = acc[i][j] + bs[j];
            if (DOTANH) v = tanhf(v);
            int n = n0 + j;
            if (MODE == 0) {
                C[(long)m*N + n] = v;
            } else {
                int b = m >> 8, t = m & 255;
                C[(long)t*(N*NB) + n*NB + b] = v;
            }
        }
    }
}

// ---------------- kernel 4: persistent LSTM (128 CTAs) ----------------
#define LSTM_CTAS 128
#define WP 130   // smem row stride in float4
#define HP 130

__global__ void __launch_bounds__(256, 1) lstm_kernel(
    const float* __restrict__ xw,
    const float* __restrict__ Whh,   // [2048,512]
    float* __restrict__ out, long bstr, long tstr)
{
    extern __shared__ float4 smem[];
    float4* ws = smem;               // 16*WP
    float4* hs = smem + 16*WP;       // 16*HP
    float*  gx = (float*)(smem + 16*WP + 16*HP);   // 256 floats

    int tid = threadIdx.x, cta = blockIdx.x;
    int gate = tid >> 6, dl = (tid >> 4) & 3, b = tid & 15;
    int jl = gate*4 + dl;
    int j  = gate*512 + cta*4 + dl;

    // stage this CTA's 16 Whh rows into smem (once)
    for (int i = tid; i < 16*128; i += 256) {
        int r = i >> 7, c = i & 127;
        int jj = (r >> 2)*512 + cta*4 + (r & 3);
        ws[r*WP + c] = ((const float4*)Whh)[jj*128 + c];
    }
    // zero h double-buffer slot 0
    for (int i = cta*256 + tid; i < NB*DEC; i += LSTM_CTAS*256)
        g_hbuf[i] = 0.f;

    float c_reg = 0.f;
    grid_barrier();

    for (int t = 0; t < LSEQ; t++) {
        const float* hsrc = g_hbuf + (t & 1)*(NB*DEC);
        for (int i = tid; i < NB*128; i += 256) {
            int bb = i >> 7, c = i & 127;
            hs[bb*HP + c] = __ldcg(((const float4*)hsrc) + bb*128 + c);
        }
        __syncthreads();

        float acc = xw[(long)t*(G4*NB) + j*NB + b];
        const float4* wr = ws + jl*WP;
        const float4* hr = hs + b*HP;
        #pragma unroll 4
        for (int k4 = 0; k4 < 128; k4++) {
            float4 w4 = wr[k4];
            float4 h4 = hr[k4];
            acc += w4.x*h4.x + w4.y*h4.y + w4.z*h4.z + w4.w*h4.w;
        }
        gx[tid] = acc;
        __syncthreads();

        if (tid < 64) {
            float ig = sigf(gx[tid]);
            float fg = sigf(gx[64 + tid]);
            float gg = tanhf(gx[128 + tid]);
            float og = sigf(gx[192 + tid]);
            c_reg = fg*c_reg + ig*gg;
            float h = og * tanhf(c_reg);
            int ddl = tid >> 4, bb = tid & 15;
            int d = cta*4 + ddl;
            __stcg(&g_hbuf[((t+1) & 1)*(NB*DEC) + bb*DEC + d], h);
            out[bb*bstr + (long)t*tstr + d] = h;
        }
        grid_barrier();
    }
}

// ---------------- kernel 5: causal self-attention (CTA per (q,b)) ----------------
__global__ void __launch_bounds__(256) attn_kernel()
{
    __shared__ float hqs[512];
    __shared__ float sc[256];
    __shared__ float red[256];
    int q = blockIdx.x, b = blockIdx.y;
    int tid = threadIdx.x;
    int nk = q + 1;
    float* catb = g_cat + (long)b*(LSEQ*2*DEC);

    if (tid < 128)
        ((float4*)hqs)[tid] = ((const float4*)(catb + q*1024 + 512))[tid];
    __syncthreads();

    int w = tid >> 5, lane = tid & 31;
    for (int k = w; k < nk; k += 8) {
        const float4* hk = (const float4*)(catb + k*1024 + 512);
        float s = 0.f;
        #pragma unroll
        for (int i = 0; i < 4; i++) {
            float4 a = ((float4*)hqs)[lane + 32*i];
            float4 c = hk[lane + 32*i];
            s += a.x*c.x + a.y*c.y + a.z*c.z + a.w*c.w;
        }
        #pragma unroll
        for (int off = 16; off; off >>= 1) s += __shfl_xor_sync(0xffffffffu, s, off);
        if (lane == 0) sc[k] = s;
    }
    __syncthreads();

    float v = (tid < nk) ? sc[tid] : -INFINITY;
    red[tid] = v; __syncthreads();
    #pragma unroll
    for (int s = 128; s; s >>= 1) {
        if (tid < s) red[tid] = fmaxf(red[tid], red[tid+s]);
        __syncthreads();
    }
    float mx = red[0]; __syncthreads();
    float e = (tid < nk) ? __expf(v - mx) : 0.f;
    red[tid] = e; __syncthreads();
    #pragma unroll
    for (int s = 128; s; s >>= 1) {
        if (tid < s) red[tid] += red[tid+s];
        __syncthreads();
    }
    float inv = 1.f / red[0];
    __syncthreads();
    if (tid < nk) sc[tid] = e * inv;
    __syncthreads();

    float a0 = 0.f, a1 = 0.f;
    for (int k = 0; k < nk; k++) {
        float wk = sc[k];
        const float* hk = catb + k*1024 + 512;
        a0 += wk * hk[tid];
        a1 += wk * hk[tid + 256];
    }
    catb[q*1024 + tid]       = a0;
    catb[q*1024 + tid + 256] = a1;
}

// ---------------- kernel 6: fp32 -> bf16 hi/lo split ----------------
__global__ void __launch_bounds__(256) split_bf16_kernel(
    const float* __restrict__ src, __nv_bfloat16* __restrict__ hi,
    __nv_bfloat16* __restrict__ lo, int n)
{
    for (int i = blockIdx.x*256 + threadIdx.x; i < n; i += gridDim.x*256) {
        float v = src[i];
        __nv_bfloat16 h = __float2bfloat16(v);
        hi[i] = h;
        lo[i] = __float2bfloat16(v - __bfloat162float(h));
    }
}

// ---------------- kernel 7: fc2 tensor-core GEMM (bf16 hi/lo, fp32 acc) ----------------
// C[4096,32000] = (Ah+Al)[4096,512] * (Bh+Bl)[32000,512]^T + bias
// CTA tile 128x128, k-step 32, cp.async double buffer, 8 warps (warp tile 32x64)
#define FC2_KS   32
#define AST      40                       // smem row stride in bf16 (80B, conflict-free)
#define MATSZ    (128*AST)                // bf16 elems per matrix tile
#define FC2_SMEM (2*4*MATSZ*2)            // 81920 B

__device__ __forceinline__ void mma_bf16(float* c, const unsigned* a, const unsigned* b)
{
    asm volatile(
        "mma.sync.aligned.m16n8k16.row.col.f32.bf16.bf16.f32 "
        "{%0,%1,%2,%3}, {%4,%5,%6,%7}, {%8,%9}, {%0,%1,%2,%3};\n"
        : "+f"(c[0]), "+f"(c[1]), "+f"(c[2]), "+f"(c[3])
        : "r"(a[0]), "r"(a[1]), "r"(a[2]), "r"(a[3]), "r"(b[0]), "r"(b[1]));
}

__global__ void __launch_bounds__(256) fc2_mma_kernel(
    const __nv_bfloat16* __restrict__ Ah, const __nv_bfloat16* __restrict__ Al,
    const __nv_bfloat16* __restrict__ Bh, const __nv_bfloat16* __restrict__ Bl,
    const float* __restrict__ bias, float* __restrict__ C)
{
    extern __shared__ __nv_bfloat16 sm[];
    const int tid = threadIdx.x;
    const int lane = tid & 31;
    const int warp = tid >> 5;
    const int warp_m = warp >> 1;        // 0..3 -> rows 32*warp_m
    const int warp_n = warp & 1;         // 0..1 -> cols 64*warp_n
    const int m0 = blockIdx.y * 128;
    const int n0 = blockIdx.x * 128;

    unsigned sbase = (unsigned)__cvta_generic_to_shared(sm);

    const __nv_bfloat16* gsrc0 = Ah + (long)m0*DEC;
    const __nv_bfloat16* gsrc1 = Al + (long)m0*DEC;
    const __nv_bfloat16* gsrc2 = Bh + (long)n0*DEC;
    const __nv_bfloat16* gsrc3 = Bl + (long)n0*DEC;

    // issue cp.async (16B each) for one k-chunk into buffer `buf`
    auto issue_load = [&](int buf, int k0) {
        const __nv_bfloat16* gs[4] = {gsrc0, gsrc1, gsrc2, gsrc3};
        #pragma unroll
        for (int mat = 0; mat < 4; mat++) {
            #pragma unroll
            for (int rep = 0; rep < 2; rep++) {
                int idx  = tid + rep*256;            // 0..511
                int row  = idx >> 2;
                int quad = idx & 3;
                unsigned daddr = sbase + ((buf*4 + mat)*MATSZ + row*AST + quad*8)*2;
                const void* g = gs[mat] + (long)row*DEC + k0 + quad*8;
                asm volatile("cp.async.cg.shared.global [%0], [%1], 16;\n"
                             :: "r"(daddr), "l"(g));
            }
        }
        asm volatile("cp.async.commit_group;\n");
    };

    float acc[2][8][4];
    #pragma unroll
    for (int i = 0; i < 2; i++)
        #pragma unroll
        for (int j = 0; j < 8; j++)
            #pragma unroll
            for (int r = 0; r < 4; r++) acc[i][j][r] = 0.f;

    issue_load(0, 0);

    int buf = 0;
    for (int ks = 0; ks < DEC/FC2_KS; ks++) {
        asm volatile("cp.async.wait_group 0;\n");
        __syncthreads();
        if (ks + 1 < DEC/FC2_KS) issue_load(buf ^ 1, (ks+1)*FC2_KS);

        const __nv_bfloat16* sAh = sm + (buf*4 + 0)*MATSZ;
        const __nv_bfloat16* sAl = sm + (buf*4 + 1)*MATSZ;
        const __nv_bfloat16* sBh = sm + (buf*4 + 2)*MATSZ;
        const __nv_bfloat16* sBl = sm + (buf*4 + 3)*MATSZ;

        #pragma unroll
        for (int k16 = 0; k16 < 2; k16++) {
            int kc = k16*16 + (lane & 3)*2;
            unsigned a_h[2][4], a_l[2][4];
            #pragma unroll
            for (int im = 0; im < 2; im++) {
                int row = warp_m*32 + im*16 + (lane >> 2);
                a_h[im][0] = *(const unsigned*)(sAh + row*AST + kc);
                a_h[im][1] = *(const unsigned*)(sAh + (row+8)*AST + kc);
                a_h[im][2] = *(const unsigned*)(sAh + row*AST + kc + 8);
                a_h[im][3] = *(const unsigned*)(sAh + (row+8)*AST + kc + 8);
                a_l[im][0] = *(const unsigned*)(sAl + row*AST + kc);
                a_l[im][1] = *(const unsigned*)(sAl + (row+8)*AST + kc);
                a_l[im][2] = *(const unsigned*)(sAl + row*AST + kc + 8);
                a_l[im][3] = *(const unsigned*)(sAl + (row+8)*AST + kc + 8);
            }
            unsigned b_h[8][2], b_l[8][2];
            #pragma unroll
            for (int in = 0; in < 8; in++) {
                int col = warp_n*64 + in*8 + (lane >> 2);
                b_h[in][0] = *(const unsigned*)(sBh + col*AST + kc);
                b_h[in][1] = *(const unsigned*)(sBh + col*AST + kc + 8);
                b_l[in][0] = *(const unsigned*)(sBl + col*AST + kc);
                b_l[in][1] = *(const unsigned*)(sBl + col*AST + kc + 8);
            }
            #pragma unroll
            for (int im = 0; im < 2; im++)
                #pragma unroll
                for (int in = 0; in < 8; in++) {
                    mma_bf16(acc[im][in], a_h[im], b_h[in]);
                    mma_bf16(acc[im][in], a_h[im], b_l[in]);
                    mma_bf16(acc[im][in], a_l[im], b_h[in]);
                }
        }
        buf ^= 1;
        __syncthreads();
    }

    // epilogue: add bias, store fp32
    #pragma unroll
    for (int im = 0; im < 2; im++) {
        int row = m0 + warp_m*32 + im*16 + (lane >> 2);
        #pragma unroll
        for (int in = 0; in < 8; in++) {
            int col = n0 + warp_n*64 + in*8 + (lane & 3)*2;
            float b0 = bias[col], b1 = bias[col+1];
            float2 v0 = make_float2(acc[im][in][0] + b0, acc[im][in][1] + b1);
            float2 v1 = make_float2(acc[im][in][2] + b0, acc[im][in][3] + b1);
            *(float2*)(C + (long)row*NV + col)     = v0;
            *(float2*)(C + (long)(row+8)*NV + col) = v1;
        }
    }
}

// ---------------- launch ----------------
extern "C" void kernel_launch(void* const* d_in, const int* in_sizes, int n_in,
                              void* d_out, int out_size)
{
    const float* x       = (const float*)d_in[0];
    const int*   y       = (const int*)  d_in[1];
    const float* fc1_w   = (const float*)d_in[2];
    const float* fc1_b   = (const float*)d_in[3];
    const float* bn_g    = (const float*)d_in[4];
    const float* bn_b    = (const float*)d_in[5];
    const float* emb     = (const float*)d_in[6];
    const float* l1_Wih  = (const float*)d_in[7];
    const float* l1_Whh  = (const float*)d_in[8];
    const float* l1_bih  = (const float*)d_in[9];
    const float* l1_bhh  = (const float*)d_in[10];
    const float* attn_W  = (const float*)d_in[11];
    const float* dc_Wih  = (const float*)d_in[12];
    const float* dc_Whh  = (const float*)d_in[13];
    const float* dc_bih  = (const float*)d_in[14];
    const float* dc_bhh  = (const float*)d_in[15];
    const float* fc2_w   = (const float*)d_in[16];
    const float* fc2_b   = (const float*)d_in[17];
    float* out = (float*)d_out;

    float *p_seq, *p_xw, *p_cat, *p_attn, *p_h2;
    __nv_bfloat16 *p_Ah, *p_Al, *p_Bh, *p_Bl;
    cudaGetSymbolAddress((void**)&p_seq,  g_seq);
    cudaGetSymbolAddress((void**)&p_xw,   g_xw);
    cudaGetSymbolAddress((void**)&p_cat,  g_cat);
    cudaGetSymbolAddress((void**)&p_attn, g_attn);
    cudaGetSymbolAddress((void**)&p_h2,   g_h2);
    cudaGetSymbolAddress((void**)&p_Ah,   g_Ah);
    cudaGetSymbolAddress((void**)&p_Al,   g_Al);
    cudaGetSymbolAddress((void**)&p_Bh,   g_Bh);
    cudaGetSymbolAddress((void**)&p_Bl,   g_Bl);

    int lstm_smem = (16*WP + 16*HP)*16 + 256*4;
    cudaFuncSetAttribute(lstm_kernel, cudaFuncAttributeMaxDynamicSharedMemorySize, lstm_smem);
    cudaFuncSetAttribute(fc2_mma_kernel, cudaFuncAttributeMaxDynamicSharedMemorySize, FC2_SMEM);

    // 1. fc1 + BN
    fc1_bn_kernel<<<1, 256>>>(x, fc1_w, fc1_b, bn_g, bn_b);
    // 2. embedding
    embed_kernel<<<NB*(LSEQ-1), 64>>>(y, emb);
    // (split fc2 weights while the front of the pipeline runs)
    split_bf16_kernel<<<2048, 256>>>(fc2_w, p_Bh, p_Bl, NV*DEC);
    // 3. xw1 = seq @ l1_Wih^T + biases   (LSTM layout)
    sgemm_tn<1,false><<<dim3(G4/128, MROWS/128), 256>>>(
        p_seq, l1_Wih, l1_bih, l1_bhh, p_xw, MROWS, G4, EMB);
    // 4. LSTM 1  ->  g_cat[b][t][512:1024]
    lstm_kernel<<<LSTM_CTAS, 256, lstm_smem>>>(
        p_xw, l1_Whh, p_cat + 512, (long)LSEQ*2*DEC, (long)2*DEC);
    // 5. attention -> g_cat[b][t][0:512]
    attn_kernel<<<dim3(LSEQ, NB), 256>>>();
    // 6. attn = tanh(cat @ attn_W^T)
    sgemm_tn<0,true><<<dim3(DEC/128, MROWS/128), 256>>>(
        p_cat, attn_W, nullptr, nullptr, p_attn, MROWS, DEC, 2*DEC);
    // 7. xw2 = attn @ dc_Wih^T + biases  (LSTM layout)
    sgemm_tn<1,false><<<dim3(G4/128, MROWS/128), 256>>>(
        p_attn, dc_Wih, dc_bih, dc_bhh, p_xw, MROWS, G4, DEC);
    // 8. LSTM 2 -> g_h2[m][d]
    lstm_kernel<<<LSTM_CTAS, 256, lstm_smem>>>(
        p_xw, dc_Whh, p_h2, (long)LSEQ*DEC, (long)DEC);
    // 9. split h2 into bf16 hi/lo
    split_bf16_kernel<<<1024, 256>>>(p_h2, p_Ah, p_Al, MROWS*DEC);
    // 10. fc2 tensor-core GEMM -> d_out
    fc2_mma_kernel<<<dim3(NV/128, MROWS/128), 256, FC2_SMEM>>>(
        p_Ah, p_Al, p_Bh, p_Bl, fc2_b, out);
}